// round 7
// baseline (speedup 1.0000x reference)
#include <cuda_runtime.h>
#include <math.h>
#include <stdint.h>

// ---------------- problem constants ----------------
// B=64, T_IN=1000, C_IN=4, F=320, K=26, POOL=13, T_CONV=975, T_POOL=75
// H=320, 3H=960, FLAT=48000, D1=2000, D2=301
static const int KSPLIT_D1 = 50;   // 48000 -> chunks of 960

// ---------------- device scratch (no allocations allowed) ----------------
__device__ float g_convout[62400 * 320];        // (B*975, 320) conv+relu
__device__ float g_pooled [4800 * 320];         // (B*75, 320)
__device__ float g_mx     [2 * 4800 * 960];     // x-projections fw|bw, row = b*75+t
__device__ float g_h      [4 * 64 * 320];       // [dir][buf] double-buffered hidden
__device__ float g_mipart [5 * 2 * 64 * 960];   // split-K partials of h@rk
__device__ float g_y      [64 * 48000];         // concat GRU output
__device__ float g_part1  [50 * 64 * 2000];     // dense1 split-K partials
__device__ float g_a1     [64 * 2000];          // dense1 activation

// ---------------- generic tiled fp32 GEMM ----------------
// AMODE: 0 = A[row*lda + k]; 1 = conv im2col view: A[(row/975)*4000 + (row%975)*4 + k]
// EPI:   0 = raw store; 1 = bias + relu; 2 = bias
// kchunk > 0: split-K over blockIdx.z, partial written at C + z*M*ldc (no bias).
template<int BM,int BN,int BK,int TM,int TN,int AMODE,int EPI>
__global__ __launch_bounds__(256)
void gemm_tiled(const float* __restrict__ A, const float* __restrict__ Bm,
                const float* __restrict__ bias, float* __restrict__ C,
                int M, int N, int K, int lda, int ldb, int ldc, int kchunk)
{
    constexpr int TX = BN / TN, TY = BM / TM;
    static_assert(TX * TY == 256, "block must be 256 threads");
    __shared__ float sA[BK][BM + 1];
    __shared__ float sB[BK][BN];

    const int tid = threadIdx.x;
    const int tx = tid % TX, ty = tid / TX;
    const int m0 = blockIdx.y * BM;
    const int n0 = blockIdx.x * BN;

    int kb = 0, ke = K;
    float* Cout = C;
    if (kchunk > 0) {
        kb = blockIdx.z * kchunk;
        ke = min(K, kb + kchunk);
        Cout = C + (size_t)blockIdx.z * (size_t)M * (size_t)ldc;
    }

    float acc[TM][TN];
#pragma unroll
    for (int i = 0; i < TM; i++)
#pragma unroll
        for (int j = 0; j < TN; j++) acc[i][j] = 0.f;

    for (int k0 = kb; k0 < ke; k0 += BK) {
#pragma unroll
        for (int l = 0; l < BM * BK / 256; l++) {
            int idx = tid + l * 256;
            int r = idx / BK, kk = idx % BK;
            int row = m0 + r, k = k0 + kk;
            float v = 0.f;
            if (row < M && k < ke) {
                size_t off;
                if (AMODE == 1) off = (size_t)(row / 975) * 4000 + (size_t)(row % 975) * 4;
                else            off = (size_t)row * (size_t)lda;
                v = A[off + k];
            }
            sA[kk][r] = v;
        }
#pragma unroll
        for (int l = 0; l < BK * BN / 256; l++) {
            int idx = tid + l * 256;
            int kk = idx / BN, c = idx % BN;
            int k = k0 + kk, col = n0 + c;
            sB[kk][c] = (k < ke && col < N) ? Bm[(size_t)k * (size_t)ldb + col] : 0.f;
        }
        __syncthreads();
#pragma unroll
        for (int kk = 0; kk < BK; kk++) {
            float ra[TM], rb[TN];
#pragma unroll
            for (int i = 0; i < TM; i++) ra[i] = sA[kk][ty * TM + i];
#pragma unroll
            for (int j = 0; j < TN; j++) rb[j] = sB[kk][tx * TN + j];
#pragma unroll
            for (int i = 0; i < TM; i++)
#pragma unroll
                for (int j = 0; j < TN; j++) acc[i][j] = fmaf(ra[i], rb[j], acc[i][j]);
        }
        __syncthreads();
    }

#pragma unroll
    for (int i = 0; i < TM; i++) {
        int row = m0 + ty * TM + i;
        if (row >= M) continue;
#pragma unroll
        for (int j = 0; j < TN; j++) {
            int col = n0 + tx * TN + j;
            if (col >= N) continue;
            float v = acc[i][j];
            if (EPI == 1)      v = fmaxf(v + bias[col], 0.f);
            else if (EPI == 2) v = v + bias[col];
            Cout[(size_t)row * (size_t)ldc + col] = v;
        }
    }
}

// ---------------- relu already applied; maxpool over 13 conv rows ----------------
__global__ __launch_bounds__(256)
void pool_kernel(const float* __restrict__ conv, float* __restrict__ pooled)
{
    int idx = blockIdx.x * 256 + threadIdx.x;
    if (idx >= 4800 * 320) return;
    int f = idx % 320;
    int bp = idx / 320;
    int b = bp / 75, p = bp % 75;
    const float* src = conv + ((size_t)(b * 975 + p * 13)) * 320 + f;
    float m = src[0];
#pragma unroll
    for (int q = 1; q < 13; q++) m = fmaxf(m, src[(size_t)q * 320]);
    pooled[idx] = m;
}

// ---------------- GRU step stage 1: mi_part[z][dir] = h_dir @ rk_dir (K split 5x64) ----------------
// grid: (15 col-chunks of 64, 2 dirs, 5 k-splits), 256 threads
__global__ __launch_bounds__(256)
void gru_s1(const float* __restrict__ h_fw, const float* __restrict__ h_bw,
            const float* __restrict__ rk_fw, const float* __restrict__ rk_bw,
            float* __restrict__ mipart)
{
    const int dir = blockIdx.y;
    const float* A  = dir ? h_bw : h_fw;     // (64, 320)
    const float* Bm = dir ? rk_bw : rk_fw;   // (320, 960)
    const int n0 = blockIdx.x * 64;
    const int k0b = blockIdx.z * 64;

    __shared__ float sA[16][65];
    __shared__ float sB[16][64];
    const int tid = threadIdx.x;
    const int tx = tid % 16, ty = tid / 16;

    float acc[4][4];
#pragma unroll
    for (int i = 0; i < 4; i++)
#pragma unroll
        for (int j = 0; j < 4; j++) acc[i][j] = 0.f;

    for (int kt = 0; kt < 4; kt++) {
        int k0 = k0b + kt * 16;
#pragma unroll
        for (int l = 0; l < 4; l++) {
            int idx = tid + l * 256;
            int r = idx / 16, kk = idx % 16;
            sA[kk][r] = A[r * 320 + k0 + kk];
        }
#pragma unroll
        for (int l = 0; l < 4; l++) {
            int idx = tid + l * 256;
            int kk = idx / 64, c = idx % 64;
            sB[kk][c] = Bm[(k0 + kk) * 960 + n0 + c];
        }
        __syncthreads();
#pragma unroll
        for (int kk = 0; kk < 16; kk++) {
            float ra[4], rb[4];
#pragma unroll
            for (int i = 0; i < 4; i++) ra[i] = sA[kk][ty * 4 + i];
#pragma unroll
            for (int j = 0; j < 4; j++) rb[j] = sB[kk][tx * 4 + j];
#pragma unroll
            for (int i = 0; i < 4; i++)
#pragma unroll
                for (int j = 0; j < 4; j++) acc[i][j] = fmaf(ra[i], rb[j], acc[i][j]);
        }
        __syncthreads();
    }

    float* Cp = mipart + ((size_t)(blockIdx.z * 2 + dir) * 64) * 960;
#pragma unroll
    for (int i = 0; i < 4; i++)
#pragma unroll
        for (int j = 0; j < 4; j++)
            Cp[(ty * 4 + i) * 960 + n0 + tx * 4 + j] = acc[i][j];
}

// ---------------- GRU step stage 2: gates (Keras reset_after=True) ----------------
__device__ __forceinline__ float sigmoidf_(float x) { return 1.f / (1.f + expf(-x)); }

__global__ __launch_bounds__(256)
void gru_gate(int s, const float* __restrict__ mipart,
              const float* __restrict__ mx_fw, const float* __restrict__ mx_bw,
              const float* __restrict__ b_fw, const float* __restrict__ b_bw,
              float* __restrict__ h, float* __restrict__ y)
{
    int idx = blockIdx.x * 256 + threadIdx.x;
    if (idx >= 2 * 64 * 320) return;
    int dir = idx / 20480;
    int rem = idx % 20480;        // b*320 + c
    int b = rem / 320, c = rem % 320;
    int t = dir ? (74 - s) : s;

    const float* mx = (dir ? mx_bw : mx_fw) + (size_t)(b * 75 + t) * 960;
    const float* br = (dir ? b_bw : b_fw) + 960;   // recurrent bias row

    float sz = 0.f, sr = 0.f, sh = 0.f;
#pragma unroll
    for (int z = 0; z < 5; z++) {
        const float* p = mipart + ((size_t)(z * 2 + dir) * 64 + b) * 960;
        sz += p[c];
        sr += p[c + 320];
        sh += p[c + 640];
    }

    int cur = s & 1, nxt = cur ^ 1;
    float hold = h[(dir * 2 + cur) * 20480 + rem];

    float zg = sigmoidf_(mx[c]       + sz + br[c]);
    float rg = sigmoidf_(mx[320 + c] + sr + br[320 + c]);
    float hh = sh + br[640 + c];
    float cand = tanhf(mx[640 + c] + rg * hh);
    float hn = zg * hold + (1.f - zg) * cand;

    h[(dir * 2 + nxt) * 20480 + rem] = hn;
    y[(size_t)b * 48000 + (size_t)t * 640 + dir * 320 + c] = hn;
}

// ---------------- dense1 split-K reduce + bias + relu ----------------
__global__ __launch_bounds__(256)
void reduce_relu(const float* __restrict__ part, const float* __restrict__ bias,
                 float* __restrict__ out)
{
    int i = blockIdx.x * 256 + threadIdx.x;
    if (i >= 64 * 2000) return;
    float s = bias[i % 2000];
#pragma unroll 10
    for (int z = 0; z < KSPLIT_D1; z++) s += part[(size_t)z * 128000 + i];
    out[i] = fmaxf(s, 0.f);
}

// ---------------- dense2 + sigmoid ----------------
__global__ void dense2_kernel(const float* __restrict__ a1, const float* __restrict__ w2,
                              const float* __restrict__ b2, float* __restrict__ out)
{
    int n = blockIdx.x * 32 + threadIdx.x;
    int b = blockIdx.y * 8 + threadIdx.y;
    if (n >= 301) return;
    float acc = b2[n];
    const float* arow = a1 + (size_t)b * 2000;
#pragma unroll 4
    for (int k = 0; k < 2000; k++)
        acc = fmaf(arow[k], w2[(size_t)k * 301 + n], acc);
    out[(size_t)b * 301 + n] = 1.f / (1.f + expf(-acc));
}

// ---------------- launcher ----------------
extern "C" void kernel_launch(void* const* d_in, const int* in_sizes, int n_in,
                              void* d_out, int out_size)
{
    const float* inputs = (const float*)d_in[0];
    const float* conv_w = (const float*)d_in[1];
    const float* conv_b = (const float*)d_in[2];
    const float* fw_k   = (const float*)d_in[3];
    const float* fw_rk  = (const float*)d_in[4];
    const float* fw_b   = (const float*)d_in[5];
    const float* bw_k   = (const float*)d_in[6];
    const float* bw_rk  = (const float*)d_in[7];
    const float* bw_b   = (const float*)d_in[8];
    const float* w1     = (const float*)d_in[9];
    const float* b1     = (const float*)d_in[10];
    const float* w2     = (const float*)d_in[11];
    const float* b2     = (const float*)d_in[12];
    float* out = (float*)d_out;

    float *convout, *pooled, *mx, *hbuf, *mipart, *ybuf, *part1, *a1;
    cudaGetSymbolAddress((void**)&convout, g_convout);
    cudaGetSymbolAddress((void**)&pooled,  g_pooled);
    cudaGetSymbolAddress((void**)&mx,      g_mx);
    cudaGetSymbolAddress((void**)&hbuf,    g_h);
    cudaGetSymbolAddress((void**)&mipart,  g_mipart);
    cudaGetSymbolAddress((void**)&ybuf,    g_y);
    cudaGetSymbolAddress((void**)&part1,   g_part1);
    cudaGetSymbolAddress((void**)&a1,      g_a1);

    // 1) Conv1D + bias + relu as GEMM on the stride-4 im2col view:
    //    A[r,kc] = inputs[(r/975)*4000 + (r%975)*4 + kc]; B = conv_w as (104,320)
    gemm_tiled<64,64,16,4,4,1,1><<<dim3(5, 975, 1), 256>>>(
        inputs, conv_w, conv_b, convout, 62400, 320, 104, 4, 320, 320, 0);

    // 2) MaxPool(13)
    pool_kernel<<<(4800 * 320 + 255) / 256, 256>>>(convout, pooled);

    // 3) GRU input projections (with input bias) for both directions
    gemm_tiled<64,128,16,4,8,0,2><<<dim3(8, 75, 1), 256>>>(
        pooled, fw_k, fw_b, mx,               4800, 960, 320, 320, 960, 960, 0);
    gemm_tiled<64,128,16,4,8,0,2><<<dim3(8, 75, 1), 256>>>(
        pooled, bw_k, bw_b, mx + 4800 * 960,  4800, 960, 320, 320, 960, 960, 0);

    // 4) zero hidden state (double-buffered, both directions)
    cudaMemsetAsync(hbuf, 0, 4 * 64 * 320 * sizeof(float));

    // 5) 75 recurrent steps: split-K recurrent GEMM (150 blocks) + fused gates
    for (int s = 0; s < 75; s++) {
        int cur = s & 1;
        gru_s1<<<dim3(15, 2, 5), 256>>>(hbuf + cur * 20480,
                                        hbuf + (2 + cur) * 20480,
                                        fw_rk, bw_rk, mipart);
        gru_gate<<<160, 256>>>(s, mipart, mx, mx + 4800 * 960, fw_b, bw_b, hbuf, ybuf);
    }

    // 6) Dense1 (64,48000)@(48000,2000): 50-way split-K, then reduce+bias+relu
    gemm_tiled<64,128,16,4,8,0,0><<<dim3(16, 1, KSPLIT_D1), 256>>>(
        ybuf, w1, (const float*)0, part1, 64, 2000, 48000, 48000, 2000, 2000, 960);
    reduce_relu<<<(64 * 2000 + 255) / 256, 256>>>(part1, b1, a1);

    // 7) Dense2 + sigmoid
    dense2_kernel<<<dim3(10, 8), dim3(32, 8)>>>(a1, w2, b2, out);

    (void)in_sizes; (void)n_in; (void)out_size;
}

// round 8
// speedup vs baseline: 1.0018x; 1.0018x over previous
#include <cuda_runtime.h>
#include <math.h>
#include <stdint.h>

// ---------------- problem constants ----------------
// B=64, T_IN=1000, C_IN=4, F=320, K=26, POOL=13, T_CONV=975, T_POOL=75
// H=320, 3H=960, FLAT=48000, D1=2000, D2=301
static const int KSPLIT_D1 = 50;   // 48000 -> chunks of 960

// ---------------- device scratch (no allocations allowed) ----------------
__device__ float g_convout[62400 * 320];        // (B*975, 320) conv+relu
__device__ float g_pooled [4800 * 320];         // (B*75, 320)
__device__ float g_mx     [2 * 4800 * 960];     // x-projections fw|bw, row = b*75+t
__device__ float g_h      [4 * 64 * 320];       // [dir][buf] double-buffered hidden
__device__ float g_mipart [5 * 2 * 64 * 960];   // split-K partials of h@rk
__device__ float g_y      [64 * 48000];         // concat GRU output
__device__ float g_part1  [50 * 64 * 2000];     // dense1 split-K partials
__device__ float g_a1     [64 * 2000];          // dense1 activation

// ---------------- generic tiled fp32 GEMM ----------------
// AMODE: 0 = A[row*lda + k]; 1 = conv im2col view: A[(row/975)*4000 + (row%975)*4 + k]
// EPI:   0 = raw store; 1 = bias + relu; 2 = bias
// kchunk > 0: split-K over blockIdx.z, partial written at C + z*M*ldc (no bias).
template<int BM,int BN,int BK,int TM,int TN,int AMODE,int EPI>
__global__ __launch_bounds__(256)
void gemm_tiled(const float* __restrict__ A, const float* __restrict__ Bm,
                const float* __restrict__ bias, float* __restrict__ C,
                int M, int N, int K, int lda, int ldb, int ldc, int kchunk)
{
    constexpr int TX = BN / TN, TY = BM / TM;
    static_assert(TX * TY == 256, "block must be 256 threads");
    __shared__ float sA[BK][BM + 1];
    __shared__ float sB[BK][BN];

    const int tid = threadIdx.x;
    const int tx = tid % TX, ty = tid / TX;
    const int m0 = blockIdx.y * BM;
    const int n0 = blockIdx.x * BN;

    int kb = 0, ke = K;
    float* Cout = C;
    if (kchunk > 0) {
        kb = blockIdx.z * kchunk;
        ke = min(K, kb + kchunk);
        Cout = C + (size_t)blockIdx.z * (size_t)M * (size_t)ldc;
    }

    float acc[TM][TN];
#pragma unroll
    for (int i = 0; i < TM; i++)
#pragma unroll
        for (int j = 0; j < TN; j++) acc[i][j] = 0.f;

    for (int k0 = kb; k0 < ke; k0 += BK) {
#pragma unroll
        for (int l = 0; l < BM * BK / 256; l++) {
            int idx = tid + l * 256;
            int r = idx / BK, kk = idx % BK;
            int row = m0 + r, k = k0 + kk;
            float v = 0.f;
            if (row < M && k < ke) {
                size_t off;
                if (AMODE == 1) off = (size_t)(row / 975) * 4000 + (size_t)(row % 975) * 4;
                else            off = (size_t)row * (size_t)lda;
                v = A[off + k];
            }
            sA[kk][r] = v;
        }
#pragma unroll
        for (int l = 0; l < BK * BN / 256; l++) {
            int idx = tid + l * 256;
            int kk = idx / BN, c = idx % BN;
            int k = k0 + kk, col = n0 + c;
            sB[kk][c] = (k < ke && col < N) ? Bm[(size_t)k * (size_t)ldb + col] : 0.f;
        }
        __syncthreads();
#pragma unroll
        for (int kk = 0; kk < BK; kk++) {
            float ra[TM], rb[TN];
#pragma unroll
            for (int i = 0; i < TM; i++) ra[i] = sA[kk][ty * TM + i];
#pragma unroll
            for (int j = 0; j < TN; j++) rb[j] = sB[kk][tx * TN + j];
#pragma unroll
            for (int i = 0; i < TM; i++)
#pragma unroll
                for (int j = 0; j < TN; j++) acc[i][j] = fmaf(ra[i], rb[j], acc[i][j]);
        }
        __syncthreads();
    }

#pragma unroll
    for (int i = 0; i < TM; i++) {
        int row = m0 + ty * TM + i;
        if (row >= M) continue;
#pragma unroll
        for (int j = 0; j < TN; j++) {
            int col = n0 + tx * TN + j;
            if (col >= N) continue;
            float v = acc[i][j];
            if (EPI == 1)      v = fmaxf(v + bias[col], 0.f);
            else if (EPI == 2) v = v + bias[col];
            Cout[(size_t)row * (size_t)ldc + col] = v;
        }
    }
}

// ---------------- relu already applied; maxpool over 13 conv rows ----------------
__global__ __launch_bounds__(256)
void pool_kernel(const float* __restrict__ conv, float* __restrict__ pooled)
{
    int idx = blockIdx.x * 256 + threadIdx.x;
    if (idx >= 4800 * 320) return;
    int f = idx % 320;
    int bp = idx / 320;
    int b = bp / 75, p = bp % 75;
    const float* src = conv + ((size_t)(b * 975 + p * 13)) * 320 + f;
    float m = src[0];
#pragma unroll
    for (int q = 1; q < 13; q++) m = fmaxf(m, src[(size_t)q * 320]);
    pooled[idx] = m;
}

// ---------------- GRU step stage 1: mi_part[z][dir] = h_dir @ rk_dir (K split 5x64) ----------------
// grid: (15 col-chunks of 64, 2 dirs, 5 k-splits), 256 threads
__global__ __launch_bounds__(256)
void gru_s1(const float* __restrict__ h_fw, const float* __restrict__ h_bw,
            const float* __restrict__ rk_fw, const float* __restrict__ rk_bw,
            float* __restrict__ mipart)
{
    const int dir = blockIdx.y;
    const float* A  = dir ? h_bw : h_fw;     // (64, 320)
    const float* Bm = dir ? rk_bw : rk_fw;   // (320, 960)
    const int n0 = blockIdx.x * 64;
    const int k0b = blockIdx.z * 64;

    __shared__ float sA[16][65];
    __shared__ float sB[16][64];
    const int tid = threadIdx.x;
    const int tx = tid % 16, ty = tid / 16;

    float acc[4][4];
#pragma unroll
    for (int i = 0; i < 4; i++)
#pragma unroll
        for (int j = 0; j < 4; j++) acc[i][j] = 0.f;

    for (int kt = 0; kt < 4; kt++) {
        int k0 = k0b + kt * 16;
#pragma unroll
        for (int l = 0; l < 4; l++) {
            int idx = tid + l * 256;
            int r = idx / 16, kk = idx % 16;
            sA[kk][r] = A[r * 320 + k0 + kk];
        }
#pragma unroll
        for (int l = 0; l < 4; l++) {
            int idx = tid + l * 256;
            int kk = idx / 64, c = idx % 64;
            sB[kk][c] = Bm[(k0 + kk) * 960 + n0 + c];
        }
        __syncthreads();
#pragma unroll
        for (int kk = 0; kk < 16; kk++) {
            float ra[4], rb[4];
#pragma unroll
            for (int i = 0; i < 4; i++) ra[i] = sA[kk][ty * 4 + i];
#pragma unroll
            for (int j = 0; j < 4; j++) rb[j] = sB[kk][tx * 4 + j];
#pragma unroll
            for (int i = 0; i < 4; i++)
#pragma unroll
                for (int j = 0; j < 4; j++) acc[i][j] = fmaf(ra[i], rb[j], acc[i][j]);
        }
        __syncthreads();
    }

    float* Cp = mipart + ((size_t)(blockIdx.z * 2 + dir) * 64) * 960;
#pragma unroll
    for (int i = 0; i < 4; i++)
#pragma unroll
        for (int j = 0; j < 4; j++)
            Cp[(ty * 4 + i) * 960 + n0 + tx * 4 + j] = acc[i][j];
}

// ---------------- GRU step stage 2: gates (Keras reset_after=True) ----------------
__device__ __forceinline__ float sigmoidf_(float x) { return 1.f / (1.f + expf(-x)); }

__global__ __launch_bounds__(256)
void gru_gate(int s, const float* __restrict__ mipart,
              const float* __restrict__ mx_fw, const float* __restrict__ mx_bw,
              const float* __restrict__ b_fw, const float* __restrict__ b_bw,
              float* __restrict__ h, float* __restrict__ y)
{
    int idx = blockIdx.x * 256 + threadIdx.x;
    if (idx >= 2 * 64 * 320) return;
    int dir = idx / 20480;
    int rem = idx % 20480;        // b*320 + c
    int b = rem / 320, c = rem % 320;
    int t = dir ? (74 - s) : s;

    const float* mx = (dir ? mx_bw : mx_fw) + (size_t)(b * 75 + t) * 960;
    const float* br = (dir ? b_bw : b_fw) + 960;   // recurrent bias row

    float sz = 0.f, sr = 0.f, sh = 0.f;
#pragma unroll
    for (int z = 0; z < 5; z++) {
        const float* p = mipart + ((size_t)(z * 2 + dir) * 64 + b) * 960;
        sz += p[c];
        sr += p[c + 320];
        sh += p[c + 640];
    }

    int cur = s & 1, nxt = cur ^ 1;
    float hold = h[(dir * 2 + cur) * 20480 + rem];

    float zg = sigmoidf_(mx[c]       + sz + br[c]);
    float rg = sigmoidf_(mx[320 + c] + sr + br[320 + c]);
    float hh = sh + br[640 + c];
    float cand = tanhf(mx[640 + c] + rg * hh);
    float hn = zg * hold + (1.f - zg) * cand;

    h[(dir * 2 + nxt) * 20480 + rem] = hn;
    y[(size_t)b * 48000 + (size_t)t * 640 + dir * 320 + c] = hn;
}

// ---------------- dense1 split-K reduce + bias + relu ----------------
__global__ __launch_bounds__(256)
void reduce_relu(const float* __restrict__ part, const float* __restrict__ bias,
                 float* __restrict__ out)
{
    int i = blockIdx.x * 256 + threadIdx.x;
    if (i >= 64 * 2000) return;
    float s = bias[i % 2000];
#pragma unroll 10
    for (int z = 0; z < KSPLIT_D1; z++) s += part[(size_t)z * 128000 + i];
    out[i] = fmaxf(s, 0.f);
}

// ---------------- dense2 + sigmoid ----------------
__global__ void dense2_kernel(const float* __restrict__ a1, const float* __restrict__ w2,
                              const float* __restrict__ b2, float* __restrict__ out)
{
    int n = blockIdx.x * 32 + threadIdx.x;
    int b = blockIdx.y * 8 + threadIdx.y;
    if (n >= 301) return;
    float acc = b2[n];
    const float* arow = a1 + (size_t)b * 2000;
#pragma unroll 4
    for (int k = 0; k < 2000; k++)
        acc = fmaf(arow[k], w2[(size_t)k * 301 + n], acc);
    out[(size_t)b * 301 + n] = 1.f / (1.f + expf(-acc));
}

// ---------------- launcher ----------------
extern "C" void kernel_launch(void* const* d_in, const int* in_sizes, int n_in,
                              void* d_out, int out_size)
{
    const float* inputs = (const float*)d_in[0];
    const float* conv_w = (const float*)d_in[1];
    const float* conv_b = (const float*)d_in[2];
    const float* fw_k   = (const float*)d_in[3];
    const float* fw_rk  = (const float*)d_in[4];
    const float* fw_b   = (const float*)d_in[5];
    const float* bw_k   = (const float*)d_in[6];
    const float* bw_rk  = (const float*)d_in[7];
    const float* bw_b   = (const float*)d_in[8];
    const float* w1     = (const float*)d_in[9];
    const float* b1     = (const float*)d_in[10];
    const float* w2     = (const float*)d_in[11];
    const float* b2     = (const float*)d_in[12];
    float* out = (float*)d_out;

    float *convout, *pooled, *mx, *hbuf, *mipart, *ybuf, *part1, *a1;
    cudaGetSymbolAddress((void**)&convout, g_convout);
    cudaGetSymbolAddress((void**)&pooled,  g_pooled);
    cudaGetSymbolAddress((void**)&mx,      g_mx);
    cudaGetSymbolAddress((void**)&hbuf,    g_h);
    cudaGetSymbolAddress((void**)&mipart,  g_mipart);
    cudaGetSymbolAddress((void**)&ybuf,    g_y);
    cudaGetSymbolAddress((void**)&part1,   g_part1);
    cudaGetSymbolAddress((void**)&a1,      g_a1);

    // 1) Conv1D + bias + relu as GEMM on the stride-4 im2col view:
    //    A[r,kc] = inputs[(r/975)*4000 + (r%975)*4 + kc]; B = conv_w as (104,320)
    gemm_tiled<64,64,16,4,4,1,1><<<dim3(5, 975, 1), 256>>>(
        inputs, conv_w, conv_b, convout, 62400, 320, 104, 4, 320, 320, 0);

    // 2) MaxPool(13)
    pool_kernel<<<(4800 * 320 + 255) / 256, 256>>>(convout, pooled);

    // 3) GRU input projections (with input bias) for both directions
    gemm_tiled<64,128,16,4,8,0,2><<<dim3(8, 75, 1), 256>>>(
        pooled, fw_k, fw_b, mx,               4800, 960, 320, 320, 960, 960, 0);
    gemm_tiled<64,128,16,4,8,0,2><<<dim3(8, 75, 1), 256>>>(
        pooled, bw_k, bw_b, mx + 4800 * 960,  4800, 960, 320, 320, 960, 960, 0);

    // 4) zero hidden state (double-buffered, both directions)
    cudaMemsetAsync(hbuf, 0, 4 * 64 * 320 * sizeof(float));

    // 5) 75 recurrent steps: split-K recurrent GEMM (150 blocks) + fused gates
    for (int s = 0; s < 75; s++) {
        int cur = s & 1;
        gru_s1<<<dim3(15, 2, 5), 256>>>(hbuf + cur * 20480,
                                        hbuf + (2 + cur) * 20480,
                                        fw_rk, bw_rk, mipart);
        gru_gate<<<160, 256>>>(s, mipart, mx, mx + 4800 * 960, fw_b, bw_b, hbuf, ybuf);
    }

    // 6) Dense1 (64,48000)@(48000,2000): 50-way split-K, then reduce+bias+relu
    gemm_tiled<64,128,16,4,8,0,0><<<dim3(16, 1, KSPLIT_D1), 256>>>(
        ybuf, w1, (const float*)0, part1, 64, 2000, 48000, 48000, 2000, 2000, 960);
    reduce_relu<<<(64 * 2000 + 255) / 256, 256>>>(part1, b1, a1);

    // 7) Dense2 + sigmoid
    dense2_kernel<<<dim3(10, 8), dim3(32, 8)>>>(a1, w2, b2, out);

    (void)in_sizes; (void)n_in; (void)out_size;
}